// round 1
// baseline (speedup 1.0000x reference)
#include <cuda_runtime.h>
#include <cstdint>
#include <cstddef>

// Problem constants
static constexpr int Bn = 4;
static constexpr int Sn = 2048;
static constexpr int En = 1024;
static constexpr int Hn = 16;
static constexpr int Dn = 64;

// Scratch (device globals; no cudaMalloc allowed)
__device__ float g_qkv[(size_t)Bn * Sn * 3 * En];   // [B,S,3E] = 100.7 MB
__device__ float g_attn[(size_t)Bn * Sn * En];      // [B,S,E]  =  33.6 MB

// ----------------------------------------------------------------------------
// NT GEMM with bias: C[M,N] = A[M,K] @ Bw[N,K]^T + bias[N]
// A row-major [M,K], Bw row-major [N,K] (torch Linear weight layout).
// 128x128 tile, BK=8, 256 threads, 8x8 register blocking.
// ----------------------------------------------------------------------------
__global__ __launch_bounds__(256) void gemm_nt_bias(
    const float* __restrict__ A, const float* __restrict__ Bw,
    const float* __restrict__ bias, float* __restrict__ C,
    int M, int N, int K)
{
    __shared__ float As[8][128];
    __shared__ float Bs[8][128];

    const int tid = threadIdx.x;
    const int tx = tid & 15;        // 0..15 -> N direction
    const int ty = tid >> 4;        // 0..15 -> M direction
    const int bm = blockIdx.y * 128;
    const int bn = blockIdx.x * 128;

    const int lr = tid >> 1;        // 0..127 tile row for loads
    const int lk = (tid & 1) * 4;   // 0 or 4

    const float* Ap = A + (size_t)(bm + lr) * K + lk;
    const float* Bp = Bw + (size_t)(bn + lr) * K + lk;

    float acc[8][8];
#pragma unroll
    for (int i = 0; i < 8; i++)
#pragma unroll
        for (int j = 0; j < 8; j++) acc[i][j] = 0.f;

    for (int k0 = 0; k0 < K; k0 += 8) {
        float4 a4 = *(const float4*)(Ap + k0);
        float4 b4 = *(const float4*)(Bp + k0);
        __syncthreads();
        As[lk + 0][lr] = a4.x; As[lk + 1][lr] = a4.y;
        As[lk + 2][lr] = a4.z; As[lk + 3][lr] = a4.w;
        Bs[lk + 0][lr] = b4.x; Bs[lk + 1][lr] = b4.y;
        Bs[lk + 2][lr] = b4.z; Bs[lk + 3][lr] = b4.w;
        __syncthreads();
#pragma unroll
        for (int kk = 0; kk < 8; kk++) {
            float ra[8], rb[8];
            *(float4*)(ra)     = *(const float4*)&As[kk][ty * 8];
            *(float4*)(ra + 4) = *(const float4*)&As[kk][ty * 8 + 4];
            *(float4*)(rb)     = *(const float4*)&Bs[kk][tx * 8];
            *(float4*)(rb + 4) = *(const float4*)&Bs[kk][tx * 8 + 4];
#pragma unroll
            for (int i = 0; i < 8; i++)
#pragma unroll
                for (int j = 0; j < 8; j++)
                    acc[i][j] += ra[i] * rb[j];
        }
    }

#pragma unroll
    for (int i = 0; i < 8; i++) {
        const int row = bm + ty * 8 + i;
#pragma unroll
        for (int j4 = 0; j4 < 8; j4 += 4) {
            const int col = bn + tx * 8 + j4;
            float4 r;
            r.x = acc[i][j4 + 0] + bias[col + 0];
            r.y = acc[i][j4 + 1] + bias[col + 1];
            r.z = acc[i][j4 + 2] + bias[col + 2];
            r.w = acc[i][j4 + 3] + bias[col + 3];
            *(float4*)(C + (size_t)row * N + col) = r;
        }
    }
}

// ----------------------------------------------------------------------------
// Flash attention (fp32, causal). Q/K/V live interleaved inside g_qkv.
// Block: 256 threads, BQ=64 query rows, BKV=32 key rows per inner tile.
// grid = (S/BQ, H, B)
// ----------------------------------------------------------------------------
#define BQ 64
#define BKV 32

__global__ __launch_bounds__(256) void attn_kernel(
    const float* __restrict__ qkv, float* __restrict__ out)
{
    __shared__ float Qs[Dn][BQ + 4];      // transposed: [d][r]
    __shared__ float Ks[Dn][BKV + 4];     // transposed: [d][c]
    __shared__ float Vs[BKV][Dn + 4];     // [c][d]
    __shared__ float Ps[BKV][BQ + 4];     // transposed scores: [c][r]
    __shared__ float m_s[BQ], l_s[BQ], alpha_s[BQ];

    const int tid = threadIdx.x;
    const int qi = blockIdx.x;            // query tile index, 0..S/BQ-1
    const int h  = blockIdx.y;
    const int b  = blockIdx.z;
    const int q0 = qi * BQ;

    const size_t rs = (size_t)3 * En;     // qkv row stride
    const float* qbase = qkv + (size_t)b * Sn * rs + (size_t)h * Dn;
    const float* kbase = qbase + En;
    const float* vbase = qbase + 2 * En;

    // Load Q tile transposed
    for (int i = tid; i < BQ * (Dn / 4); i += 256) {
        int r = i / (Dn / 4), d4 = (i % (Dn / 4)) * 4;
        float4 v = *(const float4*)(qbase + (size_t)(q0 + r) * rs + d4);
        Qs[d4 + 0][r] = v.x; Qs[d4 + 1][r] = v.y;
        Qs[d4 + 2][r] = v.z; Qs[d4 + 3][r] = v.w;
    }
    if (tid < BQ) { m_s[tid] = -1e30f; l_s[tid] = 0.f; }

    const int tx = tid & 15;   // 0..15
    const int ty = tid >> 4;   // 0..15
    float o[4][4];
#pragma unroll
    for (int i = 0; i < 4; i++)
#pragma unroll
        for (int j = 0; j < 4; j++) o[i][j] = 0.f;

    const int ntiles = 2 * qi + 2;  // causal: kv up to q-tile end
    for (int jt = 0; jt < ntiles; jt++) {
        const int k0 = jt * BKV;
        __syncthreads();  // protect smem from previous iteration (and Q load, first iter)

        // Load K (transposed) and V tiles
        for (int i = tid; i < BKV * (Dn / 4); i += 256) {
            int r = i / (Dn / 4), d4 = (i % (Dn / 4)) * 4;
            const float* kp = kbase + (size_t)(k0 + r) * rs + d4;
            float4 k4 = *(const float4*)kp;
            Ks[d4 + 0][r] = k4.x; Ks[d4 + 1][r] = k4.y;
            Ks[d4 + 2][r] = k4.z; Ks[d4 + 3][r] = k4.w;
            float4 v4 = *(const float4*)(vbase + (size_t)(k0 + r) * rs + d4);
            *(float4*)&Vs[r][d4] = v4;
        }
        __syncthreads();

        // S = scale * Q K^T (+ causal mask), stored transposed into Ps[c][r]
        {
            const int r0 = ty * 4;
            const int c0 = tx * 2;
            float s[4][2];
#pragma unroll
            for (int i = 0; i < 4; i++) { s[i][0] = 0.f; s[i][1] = 0.f; }
#pragma unroll
            for (int kk = 0; kk < Dn; kk++) {
                float qv[4];
                *(float4*)qv = *(const float4*)&Qs[kk][r0];
                float kv0 = Ks[kk][c0];
                float kv1 = Ks[kk][c0 + 1];
#pragma unroll
                for (int i = 0; i < 4; i++) {
                    s[i][0] += qv[i] * kv0;
                    s[i][1] += qv[i] * kv1;
                }
            }
            const bool need_mask = (k0 + BKV - 1 > q0);
#pragma unroll
            for (int i = 0; i < 4; i++)
#pragma unroll
                for (int j = 0; j < 2; j++) {
                    float val = s[i][j] * 0.125f;  // 1/sqrt(64)
                    if (need_mask && (k0 + c0 + j > q0 + r0 + i)) val = -1e30f;
                    Ps[c0 + j][r0 + i] = val;
                }
        }
        __syncthreads();

        // Online softmax: 4 threads per query row (8 cols each)
        {
            const int r = tid >> 2;
            const int part = tid & 3;
            float mloc = -1e30f;
#pragma unroll
            for (int c = part * 8; c < part * 8 + 8; c++)
                mloc = fmaxf(mloc, Ps[c][r]);
            mloc = fmaxf(mloc, __shfl_xor_sync(0xffffffffu, mloc, 1));
            mloc = fmaxf(mloc, __shfl_xor_sync(0xffffffffu, mloc, 2));
            const float m_old = m_s[r];
            const float m_new = fmaxf(m_old, mloc);
            float sloc = 0.f;
#pragma unroll
            for (int c = part * 8; c < part * 8 + 8; c++) {
                float p = __expf(Ps[c][r] - m_new);
                Ps[c][r] = p;
                sloc += p;
            }
            sloc += __shfl_xor_sync(0xffffffffu, sloc, 1);
            sloc += __shfl_xor_sync(0xffffffffu, sloc, 2);
            if (part == 0) {
                const float a = __expf(m_old - m_new);
                alpha_s[r] = a;
                l_s[r] = l_s[r] * a + sloc;
                m_s[r] = m_new;
            }
        }
        __syncthreads();

        // O = O*alpha + P @ V
        {
            const int r0 = ty * 4;
            const int d0 = tx * 4;
            float al[4];
#pragma unroll
            for (int i = 0; i < 4; i++) al[i] = alpha_s[r0 + i];
#pragma unroll
            for (int i = 0; i < 4; i++)
#pragma unroll
                for (int j = 0; j < 4; j++) o[i][j] *= al[i];
#pragma unroll
            for (int c = 0; c < BKV; c++) {
                float pv[4], vv[4];
                *(float4*)pv = *(const float4*)&Ps[c][r0];
                *(float4*)vv = *(const float4*)&Vs[c][d0];
#pragma unroll
                for (int i = 0; i < 4; i++)
#pragma unroll
                    for (int j = 0; j < 4; j++)
                        o[i][j] += pv[i] * vv[j];
            }
        }
    }

    // Normalize and write: out[b, q, h*D + d]
    {
        const int r0 = ty * 4;
        const int d0 = tx * 4;
#pragma unroll
        for (int i = 0; i < 4; i++) {
            const float inv = 1.0f / l_s[r0 + i];
            float4 r;
            r.x = o[i][0] * inv; r.y = o[i][1] * inv;
            r.z = o[i][2] * inv; r.w = o[i][3] * inv;
            *(float4*)(out + ((size_t)b * Sn + q0 + r0 + i) * En + h * Dn + d0) = r;
        }
    }
}

// ----------------------------------------------------------------------------
extern "C" void kernel_launch(void* const* d_in, const int* in_sizes, int n_in,
                              void* d_out, int out_size)
{
    const float* x     = (const float*)d_in[0];  // [B,S,E]
    const float* w_in  = (const float*)d_in[1];  // [3E,E]
    const float* b_in  = (const float*)d_in[2];  // [3E]
    const float* w_out = (const float*)d_in[3];  // [E,E]
    const float* b_out = (const float*)d_in[4];  // [E]
    float* out = (float*)d_out;                  // [B,S,E]

    float* qkv = nullptr;
    float* attn = nullptr;
    cudaGetSymbolAddress((void**)&qkv, g_qkv);
    cudaGetSymbolAddress((void**)&attn, g_attn);

    const int M = Bn * Sn;  // 8192

    // 1) QKV projection: [M,3E] = x @ w_in^T + b_in
    {
        dim3 grid((3 * En) / 128, M / 128);
        gemm_nt_bias<<<grid, 256>>>(x, w_in, b_in, qkv, M, 3 * En, En);
    }

    // 2) Causal flash attention -> g_attn [B,S,E]
    {
        dim3 grid(Sn / BQ, Hn, Bn);
        attn_kernel<<<grid, 256>>>(qkv, attn);
    }

    // 3) Output projection: out = attn @ w_out^T + b_out
    {
        dim3 grid(En / 128, M / 128);
        gemm_nt_bias<<<grid, 256>>>(attn, w_out, b_out, out, M, En, En);
    }
}

// round 4
// speedup vs baseline: 1.2376x; 1.2376x over previous
#include <cuda_runtime.h>
#include <cstdint>
#include <cstddef>

// Problem constants
static constexpr int Bn = 4;
static constexpr int Sn = 2048;
static constexpr int En = 1024;
static constexpr int Hn = 16;
static constexpr int Dn = 64;

// Scratch (device globals; no cudaMalloc allowed)
__device__ float g_qkv[(size_t)Bn * Sn * 3 * En];   // [B,S,3E]
__device__ float g_attn[(size_t)Bn * Sn * En];      // [B,S,E]

__device__ __forceinline__ float tf32_rna(float x) {
    uint32_t u;
    asm("cvt.rna.tf32.f32 %0, %1;" : "=r"(u) : "f"(x));
    return __uint_as_float(u);
}

// Warp-level tf32 MMA: D(16x8) += A(16x8) * B(8x8), fp32 accumulate.
__device__ __forceinline__ void mma_tf32(float* c, const uint32_t* a, const uint32_t* b) {
    asm volatile(
        "mma.sync.aligned.m16n8k8.row.col.f32.tf32.tf32.f32 "
        "{%0,%1,%2,%3}, {%4,%5,%6,%7}, {%8,%9}, {%0,%1,%2,%3};"
        : "+f"(c[0]), "+f"(c[1]), "+f"(c[2]), "+f"(c[3])
        : "r"(a[0]), "r"(a[1]), "r"(a[2]), "r"(a[3]), "r"(b[0]), "r"(b[1]));
}

// ============================================================================
// 3xTF32 tensor-core GEMM: C[M,N] = A[M,K] @ Bw[N,K]^T + bias[N]
// 128x128 tile, BK=32, double-buffered smem, 256 threads (8 warps).
// Warp grid 4(M) x 2(N); warp tile 32x64 via m16n8k8 fragments.
// ============================================================================
static constexpr int GBM = 128, GBN = 128, GBK = 32;
static constexpr int PAD = 36;                       // BK + 4: 4r+c bank-distinct
static constexpr int TILE_F = GBM * PAD;             // floats per matrix per buf
static constexpr int STAGE_F = 4 * TILE_F;           // Ahi, Alo, Bhi, Blo
static constexpr int GEMM_SMEM = 2 * STAGE_F * 4;    // bytes = 147456

#define SM_AH(st, r, c) sm[(st) * STAGE_F + 0 * TILE_F + (r) * PAD + (c)]
#define SM_AL(st, r, c) sm[(st) * STAGE_F + 1 * TILE_F + (r) * PAD + (c)]
#define SM_BH(st, r, c) sm[(st) * STAGE_F + 2 * TILE_F + (r) * PAD + (c)]
#define SM_BL(st, r, c) sm[(st) * STAGE_F + 3 * TILE_F + (r) * PAD + (c)]

__global__ __launch_bounds__(256, 1) void gemm_mma_tf32(
    const float* __restrict__ A, const float* __restrict__ Bw,
    const float* __restrict__ bias, float* __restrict__ C,
    int M, int N, int K)
{
    extern __shared__ float sm[];
    const int tid = threadIdx.x;
    const int wid = tid >> 5;
    const int lane = tid & 31;
    const int g = lane >> 2;      // groupID 0..7
    const int t4 = lane & 3;      // threadID in group
    const int wm = wid >> 1;      // 0..3
    const int wn = wid & 1;       // 0..1
    const int bm = blockIdx.y * GBM;
    const int bn = blockIdx.x * GBN;
    const int kT = K / GBK;

    float acc[2][8][4];
#pragma unroll
    for (int mt = 0; mt < 2; mt++)
#pragma unroll
        for (int nt = 0; nt < 8; nt++)
#pragma unroll
            for (int i = 0; i < 4; i++) acc[mt][nt][i] = 0.f;

    const int lrow = tid >> 3;    // 0..31 within 128-row tile per 256-thread pass... (i>>3)
    const int lq = tid & 7;       // float4 index within 32-wide k chunk

    float4 pa[4], pb[4];

    // prologue: load tile 0
#pragma unroll
    for (int s = 0; s < 4; s++) {
        const int row = lrow + s * 32;
        pa[s] = *(const float4*)(A + (size_t)(bm + row) * K + lq * 4);
        pb[s] = *(const float4*)(Bw + (size_t)(bn + row) * K + lq * 4);
    }
    {
#pragma unroll
        for (int s = 0; s < 4; s++) {
            const int row = lrow + s * 32;
            float4 v = pa[s];
            float4 hi, lo;
            hi.x = tf32_rna(v.x); lo.x = tf32_rna(v.x - hi.x);
            hi.y = tf32_rna(v.y); lo.y = tf32_rna(v.y - hi.y);
            hi.z = tf32_rna(v.z); lo.z = tf32_rna(v.z - hi.z);
            hi.w = tf32_rna(v.w); lo.w = tf32_rna(v.w - hi.w);
            *(float4*)&SM_AH(0, row, lq * 4) = hi;
            *(float4*)&SM_AL(0, row, lq * 4) = lo;
            v = pb[s];
            hi.x = tf32_rna(v.x); lo.x = tf32_rna(v.x - hi.x);
            hi.y = tf32_rna(v.y); lo.y = tf32_rna(v.y - hi.y);
            hi.z = tf32_rna(v.z); lo.z = tf32_rna(v.z - hi.z);
            hi.w = tf32_rna(v.w); lo.w = tf32_rna(v.w - hi.w);
            *(float4*)&SM_BH(0, row, lq * 4) = hi;
            *(float4*)&SM_BL(0, row, lq * 4) = lo;
        }
    }
    __syncthreads();

    for (int j = 0; j < kT; j++) {
        const int st = j & 1;
        // issue global loads for next tile early (overlap with compute)
        if (j + 1 < kT) {
            const int k0 = (j + 1) * GBK;
#pragma unroll
            for (int s = 0; s < 4; s++) {
                const int row = lrow + s * 32;
                pa[s] = *(const float4*)(A + (size_t)(bm + row) * K + k0 + lq * 4);
                pb[s] = *(const float4*)(Bw + (size_t)(bn + row) * K + k0 + lq * 4);
            }
        }

        // compute 4 k8-steps from stage st
#pragma unroll
        for (int kb = 0; kb < GBK; kb += 8) {
            uint32_t ah[2][4], al[2][4];
#pragma unroll
            for (int mt = 0; mt < 2; mt++) {
                const int r = wm * 32 + mt * 16 + g;
                ah[mt][0] = __float_as_uint(SM_AH(st, r,     kb + t4));
                ah[mt][1] = __float_as_uint(SM_AH(st, r + 8, kb + t4));
                ah[mt][2] = __float_as_uint(SM_AH(st, r,     kb + t4 + 4));
                ah[mt][3] = __float_as_uint(SM_AH(st, r + 8, kb + t4 + 4));
                al[mt][0] = __float_as_uint(SM_AL(st, r,     kb + t4));
                al[mt][1] = __float_as_uint(SM_AL(st, r + 8, kb + t4));
                al[mt][2] = __float_as_uint(SM_AL(st, r,     kb + t4 + 4));
                al[mt][3] = __float_as_uint(SM_AL(st, r + 8, kb + t4 + 4));
            }
            uint32_t bh[8][2], bl[8][2];
#pragma unroll
            for (int nt = 0; nt < 8; nt++) {
                const int c = wn * 64 + nt * 8 + g;
                bh[nt][0] = __float_as_uint(SM_BH(st, c, kb + t4));
                bh[nt][1] = __float_as_uint(SM_BH(st, c, kb + t4 + 4));
                bl[nt][0] = __float_as_uint(SM_BL(st, c, kb + t4));
                bl[nt][1] = __float_as_uint(SM_BL(st, c, kb + t4 + 4));
            }
#pragma unroll
            for (int mt = 0; mt < 2; mt++)
#pragma unroll
                for (int nt = 0; nt < 8; nt++) {
                    mma_tf32(acc[mt][nt], ah[mt], bh[nt]);
                    mma_tf32(acc[mt][nt], ah[mt], bl[nt]);
                    mma_tf32(acc[mt][nt], al[mt], bh[nt]);
                }
        }

        if (j + 1 < kT) {
            const int so = st ^ 1;
#pragma unroll
            for (int s = 0; s < 4; s++) {
                const int row = lrow + s * 32;
                float4 v = pa[s];
                float4 hi, lo;
                hi.x = tf32_rna(v.x); lo.x = tf32_rna(v.x - hi.x);
                hi.y = tf32_rna(v.y); lo.y = tf32_rna(v.y - hi.y);
                hi.z = tf32_rna(v.z); lo.z = tf32_rna(v.z - hi.z);
                hi.w = tf32_rna(v.w); lo.w = tf32_rna(v.w - hi.w);
                *(float4*)&SM_AH(so, row, lq * 4) = hi;
                *(float4*)&SM_AL(so, row, lq * 4) = lo;
                v = pb[s];
                hi.x = tf32_rna(v.x); lo.x = tf32_rna(v.x - hi.x);
                hi.y = tf32_rna(v.y); lo.y = tf32_rna(v.y - hi.y);
                hi.z = tf32_rna(v.z); lo.z = tf32_rna(v.z - hi.z);
                hi.w = tf32_rna(v.w); lo.w = tf32_rna(v.w - hi.w);
                *(float4*)&SM_BH(so, row, lq * 4) = hi;
                *(float4*)&SM_BL(so, row, lq * 4) = lo;
            }
        }
        __syncthreads();
    }

    // epilogue: fragment -> gmem with bias
#pragma unroll
    for (int mt = 0; mt < 2; mt++) {
        const int r0 = bm + wm * 32 + mt * 16 + g;
#pragma unroll
        for (int nt = 0; nt < 8; nt++) {
            const int c0 = bn + wn * 64 + nt * 8 + t4 * 2;
            const float b0 = bias[c0];
            const float b1 = bias[c0 + 1];
            float2 v0, v1;
            v0.x = acc[mt][nt][0] + b0; v0.y = acc[mt][nt][1] + b1;
            v1.x = acc[mt][nt][2] + b0; v1.y = acc[mt][nt][3] + b1;
            *(float2*)(C + (size_t)r0 * N + c0) = v0;
            *(float2*)(C + (size_t)(r0 + 8) * N + c0) = v1;
        }
    }
}

// ----------------------------------------------------------------------------
// Flash attention (fp32, causal) — unchanged (known good)
// ----------------------------------------------------------------------------
#define BQ 64
#define BKV 32

__global__ __launch_bounds__(256) void attn_kernel(
    const float* __restrict__ qkv, float* __restrict__ out)
{
    __shared__ float Qs[Dn][BQ + 4];
    __shared__ float Ks[Dn][BKV + 4];
    __shared__ float Vs[BKV][Dn + 4];
    __shared__ float Ps[BKV][BQ + 4];
    __shared__ float m_s[BQ], l_s[BQ], alpha_s[BQ];

    const int tid = threadIdx.x;
    const int qi = blockIdx.x;
    const int h  = blockIdx.y;
    const int b  = blockIdx.z;
    const int q0 = qi * BQ;

    const size_t rs = (size_t)3 * En;
    const float* qbase = qkv + (size_t)b * Sn * rs + (size_t)h * Dn;
    const float* kbase = qbase + En;
    const float* vbase = qbase + 2 * En;

    for (int i = tid; i < BQ * (Dn / 4); i += 256) {
        int r = i / (Dn / 4), d4 = (i % (Dn / 4)) * 4;
        float4 v = *(const float4*)(qbase + (size_t)(q0 + r) * rs + d4);
        Qs[d4 + 0][r] = v.x; Qs[d4 + 1][r] = v.y;
        Qs[d4 + 2][r] = v.z; Qs[d4 + 3][r] = v.w;
    }
    if (tid < BQ) { m_s[tid] = -1e30f; l_s[tid] = 0.f; }

    const int tx = tid & 15;
    const int ty = tid >> 4;
    float o[4][4];
#pragma unroll
    for (int i = 0; i < 4; i++)
#pragma unroll
        for (int j = 0; j < 4; j++) o[i][j] = 0.f;

    const int ntiles = 2 * qi + 2;
    for (int jt = 0; jt < ntiles; jt++) {
        const int k0 = jt * BKV;
        __syncthreads();

        for (int i = tid; i < BKV * (Dn / 4); i += 256) {
            int r = i / (Dn / 4), d4 = (i % (Dn / 4)) * 4;
            float4 k4 = *(const float4*)(kbase + (size_t)(k0 + r) * rs + d4);
            Ks[d4 + 0][r] = k4.x; Ks[d4 + 1][r] = k4.y;
            Ks[d4 + 2][r] = k4.z; Ks[d4 + 3][r] = k4.w;
            float4 v4 = *(const float4*)(vbase + (size_t)(k0 + r) * rs + d4);
            *(float4*)&Vs[r][d4] = v4;
        }
        __syncthreads();

        {
            const int r0 = ty * 4;
            const int c0 = tx * 2;
            float s[4][2];
#pragma unroll
            for (int i = 0; i < 4; i++) { s[i][0] = 0.f; s[i][1] = 0.f; }
#pragma unroll
            for (int kk = 0; kk < Dn; kk++) {
                float qv[4];
                *(float4*)qv = *(const float4*)&Qs[kk][r0];
                float kv0 = Ks[kk][c0];
                float kv1 = Ks[kk][c0 + 1];
#pragma unroll
                for (int i = 0; i < 4; i++) {
                    s[i][0] += qv[i] * kv0;
                    s[i][1] += qv[i] * kv1;
                }
            }
            const bool need_mask = (k0 + BKV - 1 > q0);
#pragma unroll
            for (int i = 0; i < 4; i++)
#pragma unroll
                for (int j = 0; j < 2; j++) {
                    float val = s[i][j] * 0.125f;
                    if (need_mask && (k0 + c0 + j > q0 + r0 + i)) val = -1e30f;
                    Ps[c0 + j][r0 + i] = val;
                }
        }
        __syncthreads();

        {
            const int r = tid >> 2;
            const int part = tid & 3;
            float mloc = -1e30f;
#pragma unroll
            for (int c = part * 8; c < part * 8 + 8; c++)
                mloc = fmaxf(mloc, Ps[c][r]);
            mloc = fmaxf(mloc, __shfl_xor_sync(0xffffffffu, mloc, 1));
            mloc = fmaxf(mloc, __shfl_xor_sync(0xffffffffu, mloc, 2));
            const float m_old = m_s[r];
            const float m_new = fmaxf(m_old, mloc);
            float sloc = 0.f;
#pragma unroll
            for (int c = part * 8; c < part * 8 + 8; c++) {
                float p = __expf(Ps[c][r] - m_new);
                Ps[c][r] = p;
                sloc += p;
            }
            sloc += __shfl_xor_sync(0xffffffffu, sloc, 1);
            sloc += __shfl_xor_sync(0xffffffffu, sloc, 2);
            if (part == 0) {
                const float a = __expf(m_old - m_new);
                alpha_s[r] = a;
                l_s[r] = l_s[r] * a + sloc;
                m_s[r] = m_new;
            }
        }
        __syncthreads();

        {
            const int r0 = ty * 4;
            const int d0 = tx * 4;
            float al[4];
#pragma unroll
            for (int i = 0; i < 4; i++) al[i] = alpha_s[r0 + i];
#pragma unroll
            for (int i = 0; i < 4; i++)
#pragma unroll
                for (int j = 0; j < 4; j++) o[i][j] *= al[i];
#pragma unroll
            for (int c = 0; c < BKV; c++) {
                float pv[4], vv[4];
                *(float4*)pv = *(const float4*)&Ps[c][r0];
                *(float4*)vv = *(const float4*)&Vs[c][d0];
#pragma unroll
                for (int i = 0; i < 4; i++)
#pragma unroll
                    for (int j = 0; j < 4; j++)
                        o[i][j] += pv[i] * vv[j];
            }
        }
    }

    {
        const int r0 = ty * 4;
        const int d0 = tx * 4;
#pragma unroll
        for (int i = 0; i < 4; i++) {
            const float inv = 1.0f / l_s[r0 + i];
            float4 r;
            r.x = o[i][0] * inv; r.y = o[i][1] * inv;
            r.z = o[i][2] * inv; r.w = o[i][3] * inv;
            *(float4*)(out + ((size_t)b * Sn + q0 + r0 + i) * En + h * Dn + d0) = r;
        }
    }
}

// ----------------------------------------------------------------------------
extern "C" void kernel_launch(void* const* d_in, const int* in_sizes, int n_in,
                              void* d_out, int out_size)
{
    const float* x     = (const float*)d_in[0];
    const float* w_in  = (const float*)d_in[1];
    const float* b_in  = (const float*)d_in[2];
    const float* w_out = (const float*)d_in[3];
    const float* b_out = (const float*)d_in[4];
    float* out = (float*)d_out;

    float* qkv = nullptr;
    float* attn = nullptr;
    cudaGetSymbolAddress((void**)&qkv, g_qkv);
    cudaGetSymbolAddress((void**)&attn, g_attn);

    const int M = Bn * Sn;  // 8192

    static bool attr_set = false;
    if (!attr_set) {
        cudaFuncSetAttribute(gemm_mma_tf32, cudaFuncAttributeMaxDynamicSharedMemorySize,
                             GEMM_SMEM);
        attr_set = true;
    }

    // 1) QKV projection: [M,3E] = x @ w_in^T + b_in  (3xTF32 tensor cores)
    {
        dim3 grid((3 * En) / GBN, M / GBM);
        gemm_mma_tf32<<<grid, 256, GEMM_SMEM>>>(x, w_in, b_in, qkv, M, 3 * En, En);
    }

    // 2) Causal flash attention -> g_attn [B,S,E]
    {
        dim3 grid(Sn / BQ, Hn, Bn);
        attn_kernel<<<grid, 256>>>(qkv, attn);
    }

    // 3) Output projection: out = attn @ w_out^T + b_out  (3xTF32 tensor cores)
    {
        dim3 grid(En / GBN, M / GBM);
        gemm_mma_tf32<<<grid, 256, GEMM_SMEM>>>(attn, w_out, b_out, out, M, En, En);
    }
}